// round 17
// baseline (speedup 1.0000x reference)
#include <cuda_runtime.h>
#include <cuda_bf16.h>
#include <cstdint>

// RootMLP: per-sample MLP 1->128->128->128->128->64 (SiLU), head tanh/exp.
// 4096 elements x 58048 fp32 params = 951 MB streamed once -> ~120us floor.
// R11 baseline: 154us, DRAM 79.1%. This version targets the 21% DRAM idle:
//  (1) 3-stage ring of 65KB smem buffers -> min in-flight ~130KB (was ~55KB),
//      covering loaded-DRAM latency x bandwidth product.
//  (2) work stealing via global atomic counter -> removes SM spread/tail
//      imbalance (L2-die variance floor ~1.10 + 26/27 element split).
// Counter self-resets (last finishing block) so graph replays are identical.

#define BATCH      4096
#define TP         58048
#define PADROW     132                   // 33x16B units, odd -> conflict-free LDS.128
#define WBUF_FLTS  (128 * PADROW)        // 16896
#define ABUF_FLTS  (WBUF_FLTS + 128)     // + bias

__device__ unsigned int g_ctr  = 0;      // next element to grab
__device__ unsigned int g_done = 0;      // finished blocks

__device__ __forceinline__ void cp16(float* dst_smem, const float* src_gmem) {
    uint32_t d = (uint32_t)__cvta_generic_to_shared(dst_smem);
    asm volatile("cp.async.cg.shared.global [%0], [%1], 16;\n"
                 :: "r"(d), "l"(src_gmem) : "memory");
}
__device__ __forceinline__ void cp_commit() {
    asm volatile("cp.async.commit_group;\n" ::: "memory");
}
template <int N>
__device__ __forceinline__ void cp_wait() {
    asm volatile("cp.async.wait_group %0;\n" :: "n"(N) : "memory");
}

template <int R>
__device__ __forceinline__ void load_stage(float* Wdst, float* bdst,
                                           const float* wp, int wOff, int bOff,
                                           int t) {
    #pragma unroll
    for (int c = t; c < R * 32; c += 128) {
        int r = c >> 5, cc = c & 31;
        cp16(Wdst + (r * PADROW + cc * 4), wp + wOff + c * 4);
    }
    if (t < (R >> 2))
        cp16(bdst + t * 4, wp + bOff + t * 4);
}

template <int R>
__device__ __forceinline__ float dense_row(const float* Wb, const float* bias,
                                           const float* ysm, int t) {
    const float4* Wr  = reinterpret_cast<const float4*>(Wb + t * PADROW);
    const float4* yv4 = reinterpret_cast<const float4*>(ysm);
    float a0 = 0.f, a1 = 0.f, a2 = 0.f, a3 = 0.f;
    #pragma unroll
    for (int i = 0; i < 32; i++) {
        float4 w = Wr[i];
        float4 v = yv4[i];
        a0 = fmaf(w.x, v.x, a0);
        a1 = fmaf(w.y, v.y, a1);
        a2 = fmaf(w.z, v.z, a2);
        a3 = fmaf(w.w, v.w, a3);
    }
    return ((a0 + a1) + (a2 + a3)) + bias[t];
}

__device__ __forceinline__ float silu(float z) {
    return z / (1.0f + __expf(-z));
}

__global__ void __launch_bounds__(128, 1)
rootmlp_kernel(const float* __restrict__ x,
               const float* __restrict__ fw,
               float* __restrict__ out) {
    extern __shared__ float sm[];
    float* S = sm;                          // [0..255]   layer-0 W0+b0
    float* y = sm + 256;                    // [256..383] activations
    unsigned* nextSlot = (unsigned*)(sm + 384);
    float* b0 = sm + 512;                   // three 65KB stage buffers
    float* b1 = b0 + ABUF_FLTS;
    float* b2 = b1 + ABUF_FLTS;

    const int t = threadIdx.x;

    // Grab first element (work stealing)
    if (t == 0) *nextSlot = atomicAdd(&g_ctr, 1u);
    __syncthreads();
    unsigned e = *nextSlot;
    __syncthreads();

    if (e < BATCH) {
        float* rA = b0;  float* rB = b1;  float* rC = b2;   // roles: s1, s2, s3
        const float* wp = fw + (size_t)e * TP;

        // Prologue: 4 pending groups {s0, s1->rA, s2->rB, s3->rC}
        if (t < 64) cp16(S + t * 4, wp + t * 4);
        cp_commit();
        load_stage<128>(rA, rA + WBUF_FLTS, wp, 256,   16640, t); cp_commit();
        load_stage<128>(rB, rB + WBUF_FLTS, wp, 16768, 33152, t); cp_commit();
        load_stage<128>(rC, rC + WBUF_FLTS, wp, 33280, 49664, t); cp_commit();

        while (true) {
            // Grab next element; sync below orders the write.
            if (t == 0) *nextSlot = atomicAdd(&g_ctr, 1u);

            // L0 (reads S): retire s0
            cp_wait<3>(); __syncthreads();
            {
                float xb = x[e];
                y[t] = silu(fmaf(xb, S[t], S[128 + t]));
            }
            __syncthreads();
            const unsigned en      = *nextSlot;
            const bool     has_next = (en < BATCH);
            const float*   wpn     = fw + (size_t)en * TP;

            // L1 (reads rA = s1): retire s1
            cp_wait<2>(); __syncthreads();
            {
                float z = dense_row<128>(rA, rA + WBUF_FLTS, y, t);
                __syncthreads();
                y[t] = silu(z);
                __syncthreads();
            }
            load_stage<64>(rA, rA + WBUF_FLTS, wp, 49792, 57984, t); cp_commit(); // s4 -> rA

            // L2 (reads rB = s2): retire s2
            cp_wait<2>(); __syncthreads();
            {
                float z = dense_row<128>(rB, rB + WBUF_FLTS, y, t);
                __syncthreads();
                y[t] = silu(z);
                __syncthreads();
            }
            if (has_next) {
                if (t < 64) cp16(S + t * 4, wpn + t * 4);                  // s0'
                cp_commit();
                load_stage<128>(rB, rB + WBUF_FLTS, wpn, 256, 16640, t);   // s1' -> rB
                cp_commit();
            }

            // L3 (reads rC = s3): retire s3
            if (has_next) cp_wait<3>(); else cp_wait<1>();
            __syncthreads();
            {
                float z = dense_row<128>(rC, rC + WBUF_FLTS, y, t);
                __syncthreads();
                y[t] = silu(z);
                __syncthreads();
            }
            if (has_next) {
                load_stage<128>(rC, rC + WBUF_FLTS, wpn, 16768, 33152, t); // s2' -> rC
                cp_commit();
            }

            // L4 + head (reads rA = s4): retire s4
            if (has_next) cp_wait<3>(); else cp_wait<0>();
            __syncthreads();
            if (t < 64) {
                float z = dense_row<64>(rA, rA + WBUF_FLTS, y, t);
                float o;
                if (t < 32) {
                    o = tanhf(z);
                } else {
                    float lv = fminf(fmaxf(z, -4.0f), 4.0f);
                    o = __expf(0.5f * lv);
                }
                out[(size_t)e * 64 + t] = o;
            }
            __syncthreads();

            if (!has_next) break;
            load_stage<128>(rA, rA + WBUF_FLTS, wpn, 33280, 49664, t);     // s3' -> rA
            cp_commit();

            // Rotate roles: next iter s1 in rB, s2 in rC, s3 in rA
            float* tmp = rA; rA = rB; rB = rC; rC = tmp;
            e  = en;
            wp = wpn;
        }
    }

    // Done accounting: last block resets counters for the next graph replay.
    __syncthreads();
    if (t == 0) {
        unsigned d = atomicAdd(&g_done, 1u);
        if (d == gridDim.x - 1u) {
            g_ctr  = 0;
            g_done = 0;
            __threadfence();
        }
    }
}

extern "C" void kernel_launch(void* const* d_in, const int* in_sizes, int n_in,
                              void* d_out, int out_size) {
    // Input selection by element count (x: BATCH, fw: BATCH*TP).
    const float* x  = (const float*)d_in[0];
    const float* fw = (const float*)d_in[1];
    if (n_in >= 2 && in_sizes[0] > in_sizes[1]) {
        fw = (const float*)d_in[0];
        x  = (const float*)d_in[1];
    }
    float* out = (float*)d_out;

    // smem: 512 header floats + 3 stage buffers = 206,336 B (< 227KB max)
    const size_t smem = (size_t)(512 + 3 * ABUF_FLTS) * sizeof(float);

    int dev = 0;
    cudaGetDevice(&dev);
    int sms = 148;
    cudaDeviceGetAttribute(&sms, cudaDevAttrMultiProcessorCount, dev);
    cudaFuncSetAttribute(rootmlp_kernel,
                         cudaFuncAttributeMaxDynamicSharedMemorySize, (int)smem);

    int grid = sms;
    if (grid > BATCH) grid = BATCH;

    rootmlp_kernel<<<grid, 128, smem>>>(x, fw, out);
}